// round 16
// baseline (speedup 1.0000x reference)
#include <cuda_runtime.h>
#include <cuda_bf16.h>

// Problem constants
#define BDIM 2048   // batch rows
#define SDIM 1024   // support vectors
#define FDIM 64     // features
#define FP   32     // feature PAIRS (FDIM/2)

// Tiling
#define BM 64       // rows per block = 32 lane-pairs (r, r+32)
#define BN 32       // support cols per block
#define TN 8        // cols per warp (4 warps x 8 = 32 = BN)
#define NTHREADS 128
#define SSPLIT 32   // grid.y; each block covers 1024/32 = 32 S cols

// Feature-pair trig tables (exact identity):
//   A_f = (x_f - s_f)/2;  cosA0*cosA1 = 1/2[cos(P-Q) + cos(M-N)]
//   P=(x0+x1)/2, M=(x0-x1)/2 (per row);  Q=(s0+s1)/2, N=(s0-s1)/2 (per col)
// X table, PAIRED over rows (r, r+32), 1/2 folded in:
//   g_Xp[fp*1024 + blk*32 + q] = uint4 {
//     bf16x2(.5cosP_r, .5cosP_r32), bf16x2(.5sinP...), bf16x2(.5cosM...), bf16x2(.5sinM...) }
// S table: g_Sp[fp*1024 + j] = uint2 { bf16x2(cosQ, sinQ), bf16x2(cosN, sinN) }
__device__ __align__(16) uint4 g_Xp[FP * (BDIM / 2)];   // 512 KB
__device__ __align__(16) uint2 g_Sp[FP * SDIM];         // 256 KB

static __device__ __forceinline__ __nv_bfloat162 u2bf2(unsigned u) {
    return *reinterpret_cast<__nv_bfloat162*>(&u);
}
static __device__ __forceinline__ unsigned bf2u(__nv_bfloat162 v) {
    return *reinterpret_cast<unsigned*>(&v);
}

// ---------------------------------------------------------------------------
// Kernel A: precompute feature-pair trig tables + initialize out[i] = b[0]
//   FEATURE-PAIR-MINOR thread mapping -> coalesced float2 input reads.
// ---------------------------------------------------------------------------
__global__ void precompute_kernel(const float* __restrict__ X,
                                  const float* __restrict__ S,
                                  const float* __restrict__ b,
                                  float* __restrict__ out) {
    int idx = blockIdx.x * blockDim.x + threadIdx.x;

    const int NXP = FP * (BDIM / 2);   // 32768 uint4 entries
    const int NSP = FP * SDIM;         // 32768 uint2 entries

    if (idx < NXP) {
        int fp   = idx & (FP - 1);     // minor: coalesced feature access
        int rest = idx >> 5;           // 0..1023
        int q    = rest & 31;
        int blk  = rest >> 5;
        int r0 = blk * 64 + q;         // rows r0 and r0+32
        int f0 = fp * 2;

        float cP[2], sP[2], cM[2], sM[2];
        #pragma unroll
        for (int m = 0; m < 2; m++) {
            int r = r0 + m * 32;
            float2 xv = *(const float2*)&X[r * FDIM + f0];   // coalesced
            float P = 0.5f * (xv.x + xv.y);
            float M = 0.5f * (xv.x - xv.y);
            float sp_, cp_, sm_, cm_;
            __sincosf(P, &sp_, &cp_);
            __sincosf(M, &sm_, &cm_);
            cP[m] = 0.5f * cp_;  sP[m] = 0.5f * sp_;   // fold the 1/2
            cM[m] = 0.5f * cm_;  sM[m] = 0.5f * sm_;
        }
        uint4 v;
        v.x = bf2u(__floats2bfloat162_rn(cP[0], cP[1]));
        v.y = bf2u(__floats2bfloat162_rn(sP[0], sP[1]));
        v.z = bf2u(__floats2bfloat162_rn(cM[0], cM[1]));
        v.w = bf2u(__floats2bfloat162_rn(sM[0], sM[1]));
        g_Xp[fp * (BDIM / 2) + blk * 32 + q] = v;
    } else if (idx < NXP + NSP) {
        int e  = idx - NXP;
        int fp = e & (FP - 1);         // minor: coalesced feature access
        int j  = e >> 5;               // 0..1023
        int f0 = fp * 2;
        float2 sv = *(const float2*)&S[j * FDIM + f0];       // coalesced
        float Q = 0.5f * (sv.x + sv.y);
        float N = 0.5f * (sv.x - sv.y);
        float sq, cq, sn, cn;
        __sincosf(Q, &sq, &cq);
        __sincosf(N, &sn, &cn);
        uint2 v;
        v.x = bf2u(__floats2bfloat162_rn(cq, sq));
        v.y = bf2u(__floats2bfloat162_rn(cn, sn));
        g_Sp[fp * SDIM + j] = v;
    }

    if (idx < BDIM) {
        out[idx] = b[0];               // global atomics accumulate on top
    }
}

// ---------------------------------------------------------------------------
// Kernel B: grid (2048/64, 32) = 1024 blocks, 128 threads (4 warps).
//   smem 24.25 KB -> 8 blocks/SM; single wave.
//   Lane owns row pair (rowbase+lane, rowbase+lane+32) packed in bf16x2.
//   Warp w owns cols [w*8, w*8+8).
//   S DEDUP: per group of 4 feature-pairs, lane l loads the uint2(Q,N) for
//   (fp = g*4 + l>>3, col = col0 + (l&7)) -- ONE lane-unique LDS.64 replaces
//   16 broadcast LDS.128 wavefronts; values distributed via __shfl_sync
//   (shuffle path, not the smem crossbar). X stays a lane-unique LDS.128.
//   FMA pipe becomes the sole binder.
// ---------------------------------------------------------------------------
__global__ __launch_bounds__(NTHREADS, 8)
void qkr_main_kernel(const float* __restrict__ W,
                     float* __restrict__ out) {
    __shared__ __align__(16) uint4 sX[FP * 32];   // 16 KB  [fp*32 + q]
    __shared__ __align__(16) uint2 sS[FP * BN];   //  8 KB  [fp*32 + c]

    const int tid  = threadIdx.x;
    const int lane = tid & 31;
    const int warp = tid >> 5;          // 0..3
    const int col0 = warp * TN;         // 0,8,16,24
    const int jbase = blockIdx.y * BN;  // 32 support cols for this block

    // Fills: X 1024 uint4 (8/thread).
    #pragma unroll
    for (int e = tid; e < FP * 32; e += NTHREADS) {
        int fp = e >> 5;
        int q  = e & 31;
        sX[e] = g_Xp[fp * (BDIM / 2) + blockIdx.x * 32 + q];
    }
    // S fill: FP*BN = 1024 uint2 = 512 uint4 (4/thread); k=0..15 covers all
    // 32 cols (2 cols per uint4) per feature pair.
    #pragma unroll
    for (int e4 = tid; e4 < 512; e4 += NTHREADS) {
        int fp = e4 >> 4;
        int k  = e4 & 15;
        ((uint4*)sS)[e4] = *(const uint4*)&g_Sp[fp * SDIM + jbase + k * 2];
    }
    __syncthreads();

    // p[c] = bf16x2 running product of cos((x-s)/2) over the lane's row pair
    __nv_bfloat162 p[TN];
    const __nv_bfloat162 one2 = __float2bfloat162_rn(1.0f);
    #pragma unroll
    for (int c = 0; c < TN; c++) p[c] = one2;

    const int sfp_off = lane >> 3;      // 0..3: which fp of the group I hold
    const int scol    = lane & 7;       // 0..7: which col I hold

    #pragma unroll 2
    for (int fpg = 0; fpg < FP / 4; fpg++) {   // 8 groups of 4 feature pairs
        // lane-unique S load: (Q,N) for (fpg*4 + sfp_off, col0 + scol)
        uint2 sv = sS[(fpg * 4 + sfp_off) * BN + col0 + scol];

        #pragma unroll
        for (int fpl = 0; fpl < 4; fpl++) {
            int fp = fpg * 4 + fpl;
            uint4 xv = sX[fp * 32 + lane];      // lane-unique LDS.128
            __nv_bfloat162 hcP = u2bf2(xv.x);   // .5*cosP over row pair
            __nv_bfloat162 hsP = u2bf2(xv.y);
            __nv_bfloat162 hcM = u2bf2(xv.z);
            __nv_bfloat162 hsM = u2bf2(xv.w);

            #pragma unroll
            for (int c = 0; c < TN; c++) {
                int src = fpl * 8 + c;          // lane holding (fp, col0+c)
                unsigned qu = __shfl_sync(0xffffffffu, sv.x, src);
                unsigned nu = __shfl_sync(0xffffffffu, sv.y, src);
                __nv_bfloat162 qv = u2bf2(qu);  // (cosQ, sinQ)
                __nv_bfloat162 nv = u2bf2(nu);  // (cosN, sinN)
                // term = .5cos(P-Q) + .5cos(M-N); half-lane splats fold in
                __nv_bfloat162 t = __hmul2(hcP, __low2bfloat162(qv));
                t = __hfma2(hsP, __high2bfloat162(qv), t);
                t = __hfma2(hcM, __low2bfloat162(nv), t);
                t = __hfma2(hsM, __high2bfloat162(nv), t);
                p[c] = __hmul2(p[c], t);        // running product
            }
        }
    }

    // Epilogue in f32: K = (prod cos)^2 ; acc += W[j] * K
    float acc0 = 0.0f, acc1 = 0.0f;
    #pragma unroll
    for (int c = 0; c < TN; c++) {
        float w  = __ldg(&W[jbase + col0 + c]);
        float lo = __low2float(p[c]);
        float hi = __high2float(p[c]);
        acc0 = fmaf(w, lo * lo, acc0);
        acc1 = fmaf(w, hi * hi, acc1);
    }

    // Direct global accumulation (REDG). 128 adds/address spread in time.
    atomicAdd(&out[blockIdx.x * BM + lane],      acc0);
    atomicAdd(&out[blockIdx.x * BM + lane + 32], acc1);
}

// ---------------------------------------------------------------------------
extern "C" void kernel_launch(void* const* d_in, const int* in_sizes, int n_in,
                              void* d_out, int out_size) {
    const float* X = (const float*)d_in[0];   // [2048, 64]
    const float* S = (const float*)d_in[1];   // [1024, 64]
    const float* W = (const float*)d_in[2];   // [1, 1024]
    const float* b = (const float*)d_in[3];   // [1]
    float* out = (float*)d_out;               // [2048]

    {
        int total = FP * (BDIM / 2) + FP * SDIM;   // 65536
        int threads = 256;
        int blocks = (total + threads - 1) / threads;
        precompute_kernel<<<blocks, threads>>>(X, S, b, out);
    }
    {
        dim3 grid(BDIM / BM, SSPLIT);   // (32, 32) = 1024 blocks, single wave
        qkr_main_kernel<<<grid, NTHREADS>>>(W, out);
    }
}

// round 17
// speedup vs baseline: 1.4121x; 1.4121x over previous
#include <cuda_runtime.h>
#include <cuda_bf16.h>

// Problem constants
#define BDIM 2048   // batch rows
#define SDIM 1024   // support vectors
#define FDIM 64     // features
#define FP   32     // feature PAIRS (FDIM/2)

// Tiling
#define BM 128      // rows per block = 2 row-pairs per lane
#define BN 32       // support cols per block
#define TN 8        // cols per warp (4 warps x 8 = 32 = BN)
#define NTHREADS 128
#define SSPLIT 32   // grid.y; each block covers 1024/32 = 32 S cols

// Feature-pair trig tables (exact identity):
//   A_f = (x_f - s_f)/2;  cosA0*cosA1 = 1/2[cos(P-Q) + cos(M-N)]
//   P=(x0+x1)/2, M=(x0-x1)/2 (per row);  Q=(s0+s1)/2, N=(s0-s1)/2 (per col)
// X table, PAIRED over rows (r, r+64) within 128-row blocks, 1/2 folded in:
//   g_Xp[fp*1024 + blk*64 + q] (blk=0..15, q=0..63) = uint4 {
//     bf16x2(.5cosP_r, .5cosP_r64), bf16x2(.5sinP...), bf16x2(.5cosM...), bf16x2(.5sinM...) }
// S table: g_Sp[fp*1024 + j] = uint2 { bf16x2(cosQ, sinQ), bf16x2(cosN, sinN) }
__device__ __align__(16) uint4 g_Xp[FP * (BDIM / 2)];   // 512 KB
__device__ __align__(16) uint2 g_Sp[FP * SDIM];         // 256 KB

static __device__ __forceinline__ __nv_bfloat162 u2bf2(unsigned u) {
    return *reinterpret_cast<__nv_bfloat162*>(&u);
}
static __device__ __forceinline__ unsigned bf2u(__nv_bfloat162 v) {
    return *reinterpret_cast<unsigned*>(&v);
}

// ---------------------------------------------------------------------------
// Kernel A: precompute feature-pair trig tables + initialize out[i] = b[0]
//   FEATURE-PAIR-MINOR thread mapping -> coalesced float2 input reads.
// ---------------------------------------------------------------------------
__global__ void precompute_kernel(const float* __restrict__ X,
                                  const float* __restrict__ S,
                                  const float* __restrict__ b,
                                  float* __restrict__ out) {
    int idx = blockIdx.x * blockDim.x + threadIdx.x;

    const int NXP = FP * (BDIM / 2);   // 32768 uint4 entries
    const int NSP = FP * SDIM;         // 32768 uint2 entries

    if (idx < NXP) {
        int fp   = idx & (FP - 1);     // minor: coalesced feature access
        int rest = idx >> 5;           // 0..1023
        int q    = rest & 63;          // 0..63
        int blk  = rest >> 6;          // 0..15 (128-row blocks)
        int r0 = blk * 128 + q;        // rows r0 and r0+64
        int f0 = fp * 2;

        float cP[2], sP[2], cM[2], sM[2];
        #pragma unroll
        for (int m = 0; m < 2; m++) {
            int r = r0 + m * 64;
            float2 xv = *(const float2*)&X[r * FDIM + f0];   // coalesced
            float P = 0.5f * (xv.x + xv.y);
            float M = 0.5f * (xv.x - xv.y);
            float sp_, cp_, sm_, cm_;
            __sincosf(P, &sp_, &cp_);
            __sincosf(M, &sm_, &cm_);
            cP[m] = 0.5f * cp_;  sP[m] = 0.5f * sp_;   // fold the 1/2
            cM[m] = 0.5f * cm_;  sM[m] = 0.5f * sm_;
        }
        uint4 v;
        v.x = bf2u(__floats2bfloat162_rn(cP[0], cP[1]));
        v.y = bf2u(__floats2bfloat162_rn(sP[0], sP[1]));
        v.z = bf2u(__floats2bfloat162_rn(cM[0], cM[1]));
        v.w = bf2u(__floats2bfloat162_rn(sM[0], sM[1]));
        g_Xp[fp * (BDIM / 2) + blk * 64 + q] = v;
    } else if (idx < NXP + NSP) {
        int e  = idx - NXP;
        int fp = e & (FP - 1);         // minor: coalesced feature access
        int j  = e >> 5;               // 0..1023
        int f0 = fp * 2;
        float2 sv = *(const float2*)&S[j * FDIM + f0];       // coalesced
        float Q = 0.5f * (sv.x + sv.y);
        float N = 0.5f * (sv.x - sv.y);
        float sq, cq, sn, cn;
        __sincosf(Q, &sq, &cq);
        __sincosf(N, &sn, &cn);
        uint2 v;
        v.x = bf2u(__floats2bfloat162_rn(cq, sq));
        v.y = bf2u(__floats2bfloat162_rn(cn, sn));
        g_Sp[fp * SDIM + j] = v;
    }

    if (idx < BDIM) {
        out[idx] = b[0];               // global atomics accumulate on top
    }
}

// ---------------------------------------------------------------------------
// Kernel B: grid (2048/128, 32) = 512 blocks, 128 threads (4 warps).
//   smem 40.25 KB -> 5 blocks/SM; capacity 740 >= 512 => single wave.
//   Lane owns TWO row pairs: (lane, lane+64) and (lane+32, lane+96).
//   Warp w owns cols [w*8, w*8+8).
//   Inner iter (one feature pair, 1024 positions):
//     2 lane-unique LDS.128 (X) + 4 broadcast LDS.128 (S) = 24 wavefronts
//     + 80 bf16x2 ops  -> crossbar demand 0.6 wf/cyc at FMA saturation:
//   FMA pipe is the SOLE binder (was 1.0/1.0 co-bound at BM=64).
// ---------------------------------------------------------------------------
__global__ __launch_bounds__(NTHREADS, 5)
void qkr_main_kernel(const float* __restrict__ W,
                     float* __restrict__ out) {
    __shared__ __align__(16) uint4 sX[FP * 64];   // 32 KB  [fp*64 + q]
    __shared__ __align__(16) uint2 sS[FP * BN];   //  8 KB  [fp*32 + c]

    const int tid  = threadIdx.x;
    const int lane = tid & 31;
    const int warp = tid >> 5;          // 0..3
    const int col0 = warp * TN;         // 0,8,16,24
    const int jbase = blockIdx.y * BN;  // 32 support cols for this block

    // Fills: X 2048 uint4 (16/thread); S 512 uint4 (4/thread).
    #pragma unroll
    for (int e = tid; e < FP * 64; e += NTHREADS) {
        int fp = e >> 6;
        int q  = e & 63;
        sX[e] = g_Xp[fp * (BDIM / 2) + blockIdx.x * 64 + q];
    }
    #pragma unroll
    for (int e4 = tid; e4 < 512; e4 += NTHREADS) {
        int fp = e4 >> 4;
        int k  = e4 & 15;
        ((uint4*)sS)[e4] = *(const uint4*)&g_Sp[fp * SDIM + jbase + k * 2];
    }
    __syncthreads();

    // p0[c]: rows (lane, lane+64); p1[c]: rows (lane+32, lane+96)
    __nv_bfloat162 p0[TN], p1[TN];
    const __nv_bfloat162 one2 = __float2bfloat162_rn(1.0f);
    #pragma unroll
    for (int c = 0; c < TN; c++) { p0[c] = one2; p1[c] = one2; }

    #pragma unroll 2
    for (int fp = 0; fp < FP; fp++) {
        uint4 xv0 = sX[fp * 64 + lane];         // rows (lane, lane+64)
        uint4 xv1 = sX[fp * 64 + 32 + lane];    // rows (lane+32, lane+96)
        __nv_bfloat162 hcP0 = u2bf2(xv0.x), hsP0 = u2bf2(xv0.y);
        __nv_bfloat162 hcM0 = u2bf2(xv0.z), hsM0 = u2bf2(xv0.w);
        __nv_bfloat162 hcP1 = u2bf2(xv1.x), hsP1 = u2bf2(xv1.y);
        __nv_bfloat162 hcM1 = u2bf2(xv1.z), hsM1 = u2bf2(xv1.w);

        // S: 4 broadcast LDS.128, 2 cols per load
        const uint2* srow = &sS[fp * BN + col0];
        uint4 sa = *(const uint4*)&srow[0];
        uint4 sb = *(const uint4*)&srow[2];
        uint4 sc = *(const uint4*)&srow[4];
        uint4 sd = *(const uint4*)&srow[6];
        unsigned qn[TN * 2] = { sa.x, sa.y, sa.z, sa.w,
                                sb.x, sb.y, sb.z, sb.w,
                                sc.x, sc.y, sc.z, sc.w,
                                sd.x, sd.y, sd.z, sd.w };

        #pragma unroll
        for (int c = 0; c < TN; c++) {
            __nv_bfloat162 qv = u2bf2(qn[c * 2]);       // (cosQ, sinQ)
            __nv_bfloat162 nv = u2bf2(qn[c * 2 + 1]);   // (cosN, sinN)
            __nv_bfloat162 cQ = __low2bfloat162(qv);
            __nv_bfloat162 sQ = __high2bfloat162(qv);
            __nv_bfloat162 cN = __low2bfloat162(nv);
            __nv_bfloat162 sN = __high2bfloat162(nv);

            __nv_bfloat162 t0 = __hmul2(hcP0, cQ);
            t0 = __hfma2(hsP0, sQ, t0);
            t0 = __hfma2(hcM0, cN, t0);
            t0 = __hfma2(hsM0, sN, t0);
            p0[c] = __hmul2(p0[c], t0);

            __nv_bfloat162 t1 = __hmul2(hcP1, cQ);
            t1 = __hfma2(hsP1, sQ, t1);
            t1 = __hfma2(hcM1, cN, t1);
            t1 = __hfma2(hsM1, sN, t1);
            p1[c] = __hmul2(p1[c], t1);
        }
    }

    // Epilogue in f32: K = (prod cos)^2 ; acc += W[j] * K
    float a0 = 0.0f, a64 = 0.0f, a32 = 0.0f, a96 = 0.0f;
    #pragma unroll
    for (int c = 0; c < TN; c++) {
        float w = __ldg(&W[jbase + col0 + c]);
        float l0 = __low2float(p0[c]),  h0 = __high2float(p0[c]);
        float l1 = __low2float(p1[c]),  h1 = __high2float(p1[c]);
        a0  = fmaf(w, l0 * l0, a0);
        a64 = fmaf(w, h0 * h0, a64);
        a32 = fmaf(w, l1 * l1, a32);
        a96 = fmaf(w, h1 * h1, a96);
    }

    // Direct global accumulation (REDG). 128 adds/address spread in time.
    const int rb = blockIdx.x * BM + lane;
    atomicAdd(&out[rb],      a0);
    atomicAdd(&out[rb + 32], a32);
    atomicAdd(&out[rb + 64], a64);
    atomicAdd(&out[rb + 96], a96);
}

// ---------------------------------------------------------------------------
extern "C" void kernel_launch(void* const* d_in, const int* in_sizes, int n_in,
                              void* d_out, int out_size) {
    const float* X = (const float*)d_in[0];   // [2048, 64]
    const float* S = (const float*)d_in[1];   // [1024, 64]
    const float* W = (const float*)d_in[2];   // [1, 1024]
    const float* b = (const float*)d_in[3];   // [1]
    float* out = (float*)d_out;               // [2048]

    {
        int total = FP * (BDIM / 2) + FP * SDIM;   // 65536
        int threads = 256;
        int blocks = (total + threads - 1) / threads;
        precompute_kernel<<<blocks, threads>>>(X, S, b, out);
    }
    {
        dim3 grid(BDIM / BM, SSPLIT);   // (16, 32) = 512 blocks, single wave
        qkr_main_kernel<<<grid, NTHREADS>>>(W, out);
    }
}